// round 12
// baseline (speedup 1.0000x reference)
#include <cuda_runtime.h>
#include <cuda_fp16.h>
#include <cstdint>
#include <math.h>

#define N_ 128
#define D_ 512
#define L_ 512
#define K_ 512
#define M_ (N_ * D_)

// ---------------- device globals (allocation-free scratch) ----------------
__device__ float g_w[D_ * L_];                 // fp32 window * exp(sigma/(L-1))
__device__ __half gA[(size_t)M_ * L_];         // 67 MB, xw in fp16
__device__ __half gBc[L_ * K_];                // cos basis, fp16
__device__ __half gBs[L_ * K_];                // sin basis, fp16

// ---------------- helpers ----------------
__device__ __forceinline__ uint32_t smem_u32(const void* p) {
    uint32_t a;
    asm("{ .reg .u64 t; cvta.to.shared.u64 t, %1; cvt.u32.u64 %0, t; }" : "=r"(a) : "l"(p));
    return a;
}
#define CP_ASYNC16(dst, src) asm volatile("cp.async.cg.shared.global [%0], [%1], 16;" :: "r"(dst), "l"(src))
#define CP_COMMIT() asm volatile("cp.async.commit_group;" ::: "memory")

#define LDSM4(R, addr) \
    asm volatile("ldmatrix.sync.aligned.m8n8.x4.shared.b16 {%0,%1,%2,%3}, [%4];" \
        : "=r"((R)[0]), "=r"((R)[1]), "=r"((R)[2]), "=r"((R)[3]) : "r"(addr))
#define LDSM4T(R, addr) \
    asm volatile("ldmatrix.sync.aligned.m8n8.x4.trans.shared.b16 {%0,%1,%2,%3}, [%4];" \
        : "=r"((R)[0]), "=r"((R)[1]), "=r"((R)[2]), "=r"((R)[3]) : "r"(addr))

#define MMA16816(D, A, B0, B1) \
    asm volatile("mma.sync.aligned.m16n8k16.row.col.f32.f16.f16.f32 " \
        "{%0,%1,%2,%3}, {%4,%5,%6,%7}, {%8,%9}, {%0,%1,%2,%3};" \
        : "+f"((D)[0]), "+f"((D)[1]), "+f"((D)[2]), "+f"((D)[3]) \
        : "r"((A)[0]), "r"((A)[1]), "r"((A)[2]), "r"((A)[3]), "r"(B0), "r"(B1))

// ---------------- prep: basis (fp16) + window, then used by split_a ----------------
__global__ void precompute_kernel(const float* __restrict__ a,
                                  const float* __restrict__ sigma) {
    const int idx = blockIdx.x * blockDim.x + threadIdx.x;
    const float c = (float)(6.283185307179586 / 511.0);
    if (idx < L_ * K_) {
        const int l = idx / K_, k = idx - l * K_;
        float s, cc;
        sincosf(c * (float)(l * k), &s, &cc);
        gBc[idx] = __float2half(cc);
        gBs[idx] = __float2half(s);
    }
    if (idx < D_ * L_) {
        const int d = idx / L_, l = idx - d * L_;
        const float ad = a[d];
        const float w = ad - (1.0f - ad) * cosf(c * (float)l);
        g_w[idx] = w * expf(sigma[d] * (1.0f / 511.0f));
    }
}

// ---------------- prep 2: xw = x * w -> fp16 ----------------
__global__ __launch_bounds__(256)
void split_a_kernel(const float4* __restrict__ x) {
    const size_t g = (size_t)blockIdx.x * blockDim.x + threadIdx.x;
    if (g >= (size_t)M_ * L_ / 4) return;
    const int m  = (int)(g >> 7);
    const int l4 = (int)(g & 127);
    const int d  = m & (D_ - 1);
    const float4 xv = x[g];
    const float4 wv = *(const float4*)(g_w + (size_t)d * L_ + l4 * 4);
    __half h[4];
    h[0] = __float2half(xv.x * wv.x);
    h[1] = __float2half(xv.y * wv.y);
    h[2] = __float2half(xv.z * wv.z);
    h[3] = __float2half(xv.w * wv.w);
    ((uint2*)gA)[g] = *(uint2*)h;
}

// ---------------- main: mma.sync dual-GEMM + magnitude ----------------
// CTA tile: 256(M) x 64(N), BK=64, 16 warps (4 in M x 4 in N), warp tile 64x16.
// 512 threads, 1 CTA/SM (16 warps/SM), 3-stage cp.async, 1 barrier/chunk.
#define BK 64
#define NCH (L_ / BK)            // 8 chunks
#define NSTAGE 3
#define NT 512
#define PITCH 144                // 128B data + 16B pad (conflict-free ldmatrix)
#define SA_BYTES (256 * PITCH)   // 36864 (A tile, 256 rows)
#define SB_BYTES (64 * PITCH)    // 9216 per B matrix
#define SB_BASE SA_BYTES
#define STAGE (SA_BYTES + 2 * SB_BYTES)  // 55296
#define SMEM_TOTAL (NSTAGE * STAGE)      // 165888

__device__ __forceinline__ void load_chunk(uint32_t sbuf, int row0, int col0,
                                           int l0, int tid) {
    // A: 256 rows x 8 (16B units) = 2048 -> 4 per thread
#pragma unroll
    for (int p = 0; p < 4; ++p) {
        const int u = tid + p * NT;
        const int r = u >> 3;
        const int cu = u & 7;
        const __half* src = gA + (size_t)(row0 + r) * L_ + l0 + cu * 8;
        CP_ASYNC16(sbuf + r * PITCH + cu * 16, src);
    }
    // B: 2 matrices x 64 rows x 8 (16B units) = 1024 -> 2 per thread
#pragma unroll
    for (int p = 0; p < 2; ++p) {
        const int u = tid + p * NT;
        const int mat = u >> 9;
        const int r = (u >> 3) & 63;
        const int cu = u & 7;
        const __half* g = mat ? gBs : gBc;
        const __half* src = g + (size_t)(l0 + r) * K_ + col0 + cu * 8;
        CP_ASYNC16(sbuf + SB_BASE + mat * SB_BYTES + r * PITCH + cu * 16, src);
    }
}

__global__ __launch_bounds__(NT, 1)
void spectro_mma_kernel(float* __restrict__ out) {
    extern __shared__ char smem[];
    const uint32_t sbase = smem_u32(smem);
    const int tid = threadIdx.x;
    const int wid = tid >> 5;
    const int lid = tid & 31;
    const int col0 = blockIdx.x * 64;    // 8 col tiles
    const int row0 = blockIdx.y * 256;   // 256 row tiles
    const int wm = wid >> 2;             // 0..3 (M, 64 rows each)
    const int wn = wid & 3;              // 0..3 (N, 16 cols each)

    float accR[4][2][4];
    float accI[4][2][4];
#pragma unroll
    for (int mt = 0; mt < 4; ++mt)
#pragma unroll
        for (int nt = 0; nt < 2; ++nt)
#pragma unroll
            for (int j = 0; j < 4; ++j) { accR[mt][nt][j] = 0.f; accI[mt][nt][j] = 0.f; }

    const int g8 = lid >> 3;       // 0..3
    const int lr = lid & 7;        // row within 8x8

    // prologue: 2 chunks in flight
    load_chunk(sbase + 0 * STAGE, row0, col0, 0, tid);
    CP_COMMIT();
    load_chunk(sbase + 1 * STAGE, row0, col0, BK, tid);
    CP_COMMIT();

    for (int c = 0; c < NCH; ++c) {
        // make chunk c resident
        if (c + 1 < NCH) {
            asm volatile("cp.async.wait_group 1;" ::: "memory");
        } else {
            asm volatile("cp.async.wait_group 0;" ::: "memory");
        }
        __syncthreads();   // all warps past chunk c-1 compute; chunk c visible

        // prefetch chunk c+2 into slot (c+2)%3 == (c-1)%3 (safe post-barrier)
        if (c + 2 < NCH) {
            load_chunk(sbase + ((c + 2) % NSTAGE) * STAGE, row0, col0, (c + 2) * BK, tid);
            CP_COMMIT();
        }

        const uint32_t sa = sbase + (c % NSTAGE) * STAGE;
        const uint32_t sb = sa + SB_BASE;
#pragma unroll
        for (int kk = 0; kk < 4; ++kk) {
            uint32_t aH[4][4];
#pragma unroll
            for (int mt = 0; mt < 4; ++mt) {
                const int row = wm * 64 + mt * 16 + ((g8 & 1) << 3) + lr;
                const uint32_t ad = sa + row * PITCH + kk * 32 + ((g8 >> 1) << 4);
                LDSM4(aH[mt], ad);
            }
            const int krow = kk * 16 + ((g8 & 1) << 3) + lr;
            const uint32_t bd = sb + krow * PITCH + wn * 32 + ((g8 >> 1) << 4);
            uint32_t bC[4], bS[4];
            LDSM4T(bC, bd);
            LDSM4T(bS, bd + SB_BYTES);
#pragma unroll
            for (int mt = 0; mt < 4; ++mt) {
#pragma unroll
                for (int nt = 0; nt < 2; ++nt) {
                    MMA16816(accR[mt][nt], aH[mt], bC[nt * 2], bC[nt * 2 + 1]);
                    MMA16816(accI[mt][nt], aH[mt], bS[nt * 2], bS[nt * 2 + 1]);
                }
            }
        }
    }

    // ---- epilogue: magnitude, direct from accumulator fragments ----
#pragma unroll
    for (int mt = 0; mt < 4; ++mt) {
#pragma unroll
        for (int nt = 0; nt < 2; ++nt) {
            const int r0 = row0 + wm * 64 + mt * 16 + (lid >> 2);
            const int cc = col0 + wn * 16 + nt * 8 + (lid & 3) * 2;
            float2 o0, o1;
            o0.x = sqrtf(fmaf(accR[mt][nt][0], accR[mt][nt][0],
                              accI[mt][nt][0] * accI[mt][nt][0]));
            o0.y = sqrtf(fmaf(accR[mt][nt][1], accR[mt][nt][1],
                              accI[mt][nt][1] * accI[mt][nt][1]));
            o1.x = sqrtf(fmaf(accR[mt][nt][2], accR[mt][nt][2],
                              accI[mt][nt][2] * accI[mt][nt][2]));
            o1.y = sqrtf(fmaf(accR[mt][nt][3], accR[mt][nt][3],
                              accI[mt][nt][3] * accI[mt][nt][3]));
            *(float2*)(out + (size_t)r0 * K_ + cc) = o0;
            *(float2*)(out + (size_t)(r0 + 8) * K_ + cc) = o1;
        }
    }
}

// ---------------------------------------------------------------------------
extern "C" void kernel_launch(void* const* d_in, const int* in_sizes, int n_in,
                              void* d_out, int out_size) {
    const float* x     = (const float*)d_in[0];  // (N, D, L)
    const float* a     = (const float*)d_in[1];  // (D,)
    const float* sigma = (const float*)d_in[2];  // (D,)
    float* out = (float*)d_out;                  // (N, D, K)

    precompute_kernel<<<(L_ * K_ + 255) / 256, 256>>>(a, sigma);
    split_a_kernel<<<(M_ * L_ / 4 + 255) / 256, 256>>>((const float4*)x);

    static bool attr_set = false;
    if (!attr_set) {
        cudaFuncSetAttribute(spectro_mma_kernel,
                             cudaFuncAttributeMaxDynamicSharedMemorySize, SMEM_TOTAL);
        attr_set = true;
    }
    dim3 grid(K_ / 64, M_ / 256);   // (8, 256)
    spectro_mma_kernel<<<grid, NT, SMEM_TOTAL>>>(out);
}

// round 13
// speedup vs baseline: 1.7707x; 1.7707x over previous
#include <cuda_runtime.h>
#include <cuda_fp16.h>
#include <cstdint>
#include <math.h>

#define N_ 128
#define D_ 512
#define L_ 512
#define K_ 512
#define KH 256                   // compute half the spectrum; mirror k <-> 511-k
#define M_ (N_ * D_)

// ---------------- device globals (allocation-free scratch) ----------------
__device__ float g_w[D_ * L_];                 // fp32 window * exp(sigma/(L-1))
__device__ __half gA[(size_t)M_ * L_];         // 67 MB, xw in fp16
__device__ __half gBc[L_ * KH];                // cos basis (k<256), fp16
__device__ __half gBs[L_ * KH];                // sin basis (k<256), fp16

// ---------------- helpers ----------------
__device__ __forceinline__ uint32_t smem_u32(const void* p) {
    uint32_t a;
    asm("{ .reg .u64 t; cvta.to.shared.u64 t, %1; cvt.u32.u64 %0, t; }" : "=r"(a) : "l"(p));
    return a;
}
#define CP_ASYNC16(dst, src) asm volatile("cp.async.cg.shared.global [%0], [%1], 16;" :: "r"(dst), "l"(src))
#define CP_COMMIT() asm volatile("cp.async.commit_group;" ::: "memory")

#define LDSM4(R, addr) \
    asm volatile("ldmatrix.sync.aligned.m8n8.x4.shared.b16 {%0,%1,%2,%3}, [%4];" \
        : "=r"((R)[0]), "=r"((R)[1]), "=r"((R)[2]), "=r"((R)[3]) : "r"(addr))
#define LDSM4T(R, addr) \
    asm volatile("ldmatrix.sync.aligned.m8n8.x4.trans.shared.b16 {%0,%1,%2,%3}, [%4];" \
        : "=r"((R)[0]), "=r"((R)[1]), "=r"((R)[2]), "=r"((R)[3]) : "r"(addr))

#define MMA16816(D, A, B0, B1) \
    asm volatile("mma.sync.aligned.m16n8k16.row.col.f32.f16.f16.f32 " \
        "{%0,%1,%2,%3}, {%4,%5,%6,%7}, {%8,%9}, {%0,%1,%2,%3};" \
        : "+f"((D)[0]), "+f"((D)[1]), "+f"((D)[2]), "+f"((D)[3]) \
        : "r"((A)[0]), "r"((A)[1]), "r"((A)[2]), "r"((A)[3]), "r"(B0), "r"(B1))

// ---------------- prep 1: basis (fp16, k<256) + window (fp32) ----------------
__global__ void precompute_kernel(const float* __restrict__ a,
                                  const float* __restrict__ sigma) {
    const int idx = blockIdx.x * blockDim.x + threadIdx.x;
    const float c = (float)(6.283185307179586 / 511.0);
    if (idx < L_ * KH) {
        const int l = idx / KH, k = idx - l * KH;
        float s, cc;
        sincosf(c * (float)(l * k), &s, &cc);
        gBc[idx] = __float2half(cc);
        gBs[idx] = __float2half(s);
    }
    if (idx < D_ * L_) {
        const int d = idx / L_, l = idx - d * L_;
        const float ad = a[d];
        const float w = ad - (1.0f - ad) * cosf(c * (float)l);
        g_w[idx] = w * expf(sigma[d] * (1.0f / 511.0f));
    }
}

// ---------------- prep 2: xw = x * w -> fp16 ----------------
__global__ __launch_bounds__(256)
void split_a_kernel(const float4* __restrict__ x) {
    const size_t g = (size_t)blockIdx.x * blockDim.x + threadIdx.x;
    if (g >= (size_t)M_ * L_ / 4) return;
    const int m  = (int)(g >> 7);
    const int l4 = (int)(g & 127);
    const int d  = m & (D_ - 1);
    const float4 xv = x[g];
    const float4 wv = *(const float4*)(g_w + (size_t)d * L_ + l4 * 4);
    __half h[4];
    h[0] = __float2half(xv.x * wv.x);
    h[1] = __float2half(xv.y * wv.y);
    h[2] = __float2half(xv.z * wv.z);
    h[3] = __float2half(xv.w * wv.w);
    ((uint2*)gA)[g] = *(uint2*)h;
}

// ---------------- main: mma.sync dual-GEMM + magnitude (half spectrum) --------
// CTA tile: 128(M) x 64(N), BK=64, 8 warps (2 in M x 4 in N), warp tile 64x16.
// 2 CTAs/SM, 2-stage pipeline (R8 winning config). Epilogue mirrors k -> 511-k.
#define BK 64
#define NCH (L_ / BK)            // 8 chunks
#define PITCH 144                // 128B data + 16B pad (conflict-free ldmatrix)
#define SA_BYTES (128 * PITCH)   // 18432 (A tile)
#define SB_BYTES (64 * PITCH)    // 9216 per B matrix
#define SB_BASE SA_BYTES
#define STAGE (SA_BYTES + 2 * SB_BYTES)  // 36864
#define SMEM_TOTAL (2 * STAGE)           // 73728 -> 2 CTAs/SM

__device__ __forceinline__ void load_chunk(uint32_t sbuf, int row0, int col0,
                                           int l0, int tid) {
    // A: 128 rows x 8 (16B units) = 1024 -> 4 per thread
#pragma unroll
    for (int p = 0; p < 4; ++p) {
        const int u = tid + p * 256;
        const int r = u >> 3;
        const int cu = u & 7;
        const __half* src = gA + (size_t)(row0 + r) * L_ + l0 + cu * 8;
        CP_ASYNC16(sbuf + r * PITCH + cu * 16, src);
    }
    // B: 2 matrices x 64 rows x 8 (16B units) = 1024 -> 4 per thread
#pragma unroll
    for (int p = 0; p < 4; ++p) {
        const int u = tid + p * 256;
        const int mat = u >> 9;
        const int r = (u >> 3) & 63;
        const int cu = u & 7;
        const __half* g = mat ? gBs : gBc;
        const __half* src = g + (size_t)(l0 + r) * KH + col0 + cu * 8;
        CP_ASYNC16(sbuf + SB_BASE + mat * SB_BYTES + r * PITCH + cu * 16, src);
    }
}

__global__ __launch_bounds__(256, 2)
void spectro_mma_kernel(float* __restrict__ out) {
    extern __shared__ char smem[];
    const uint32_t sbase = smem_u32(smem);
    const int tid = threadIdx.x;
    const int wid = tid >> 5;
    const int lid = tid & 31;
    const int col0 = blockIdx.x * 64;    // 4 col tiles (k < 256)
    const int row0 = blockIdx.y * 128;   // 512 row tiles
    const int wm = wid >> 2;             // 0..1 (M)
    const int wn = wid & 3;              // 0..3 (N)

    float accR[4][2][4];
    float accI[4][2][4];
#pragma unroll
    for (int mt = 0; mt < 4; ++mt)
#pragma unroll
        for (int nt = 0; nt < 2; ++nt)
#pragma unroll
            for (int j = 0; j < 4; ++j) { accR[mt][nt][j] = 0.f; accI[mt][nt][j] = 0.f; }

    const int g8 = lid >> 3;       // 0..3
    const int lr = lid & 7;        // row within 8x8

    load_chunk(sbase, row0, col0, 0, tid);
    CP_COMMIT();

    for (int c = 0; c < NCH; ++c) {
        if (c + 1 < NCH) {
            load_chunk(sbase + ((c + 1) & 1) * STAGE, row0, col0, (c + 1) * BK, tid);
            CP_COMMIT();
            asm volatile("cp.async.wait_group 1;" ::: "memory");
        } else {
            asm volatile("cp.async.wait_group 0;" ::: "memory");
        }
        __syncthreads();

        const uint32_t sa = sbase + (c & 1) * STAGE;
        const uint32_t sb = sa + SB_BASE;
#pragma unroll
        for (int kk = 0; kk < 4; ++kk) {
            uint32_t aH[4][4];
#pragma unroll
            for (int mt = 0; mt < 4; ++mt) {
                const int row = wm * 64 + mt * 16 + ((g8 & 1) << 3) + lr;
                const uint32_t ad = sa + row * PITCH + kk * 32 + ((g8 >> 1) << 4);
                LDSM4(aH[mt], ad);
            }
            const int krow = kk * 16 + ((g8 & 1) << 3) + lr;
            const uint32_t bd = sb + krow * PITCH + wn * 32 + ((g8 >> 1) << 4);
            uint32_t bC[4], bS[4];
            LDSM4T(bC, bd);
            LDSM4T(bS, bd + SB_BYTES);
#pragma unroll
            for (int mt = 0; mt < 4; ++mt) {
#pragma unroll
                for (int nt = 0; nt < 2; ++nt) {
                    MMA16816(accR[mt][nt], aH[mt], bC[nt * 2], bC[nt * 2 + 1]);
                    MMA16816(accI[mt][nt], aH[mt], bS[nt * 2], bS[nt * 2 + 1]);
                }
            }
        }
        __syncthreads();
    }

    // ---- epilogue: magnitude; store column k and its mirror 511-k ----
#pragma unroll
    for (int mt = 0; mt < 4; ++mt) {
#pragma unroll
        for (int nt = 0; nt < 2; ++nt) {
            const int r0 = row0 + wm * 64 + mt * 16 + (lid >> 2);
            const int cc = col0 + wn * 16 + nt * 8 + (lid & 3) * 2;
            float2 o0, o1;
            o0.x = sqrtf(fmaf(accR[mt][nt][0], accR[mt][nt][0],
                              accI[mt][nt][0] * accI[mt][nt][0]));
            o0.y = sqrtf(fmaf(accR[mt][nt][1], accR[mt][nt][1],
                              accI[mt][nt][1] * accI[mt][nt][1]));
            o1.x = sqrtf(fmaf(accR[mt][nt][2], accR[mt][nt][2],
                              accI[mt][nt][2] * accI[mt][nt][2]));
            o1.y = sqrtf(fmaf(accR[mt][nt][3], accR[mt][nt][3],
                              accI[mt][nt][3] * accI[mt][nt][3]));
            float* row_a = out + (size_t)r0 * K_;
            float* row_b = out + (size_t)(r0 + 8) * K_;
            *(float2*)(row_a + cc) = o0;
            *(float2*)(row_b + cc) = o1;
            // mirror: out[., 511-cc] = o.x ; out[., 510-cc] = o.y
            float2 m0 = {o0.y, o0.x};
            float2 m1 = {o1.y, o1.x};
            *(float2*)(row_a + 510 - cc) = m0;
            *(float2*)(row_b + 510 - cc) = m1;
        }
    }
}

// ---------------------------------------------------------------------------
extern "C" void kernel_launch(void* const* d_in, const int* in_sizes, int n_in,
                              void* d_out, int out_size) {
    const float* x     = (const float*)d_in[0];  // (N, D, L)
    const float* a     = (const float*)d_in[1];  // (D,)
    const float* sigma = (const float*)d_in[2];  // (D,)
    float* out = (float*)d_out;                  // (N, D, K)

    precompute_kernel<<<(D_ * L_ + 255) / 256, 256>>>(a, sigma);
    split_a_kernel<<<(M_ * L_ / 4 + 255) / 256, 256>>>((const float4*)x);

    static bool attr_set = false;
    if (!attr_set) {
        cudaFuncSetAttribute(spectro_mma_kernel,
                             cudaFuncAttributeMaxDynamicSharedMemorySize, SMEM_TOTAL);
        attr_set = true;
    }
    dim3 grid(KH / 64, M_ / 128);   // (4, 512)
    spectro_mma_kernel<<<grid, 256, SMEM_TOTAL>>>(out);
}

// round 14
// speedup vs baseline: 2.2039x; 1.2446x over previous
#include <cuda_runtime.h>
#include <cuda_fp16.h>
#include <cstdint>
#include <math.h>

#define N_ 128
#define D_ 512
#define L_ 512
#define K_ 512
#define KH 256                   // half spectrum (k-mirror)
#define LH 256                   // half reduction (l-fold)
#define M_ (N_ * D_)

// ---------------- device globals (allocation-free scratch) ----------------
__device__ float g_w[D_ * L_];                 // fp32 window * exp(sigma/(L-1))
__device__ __half gAu[(size_t)M_ * LH];        // 33.5 MB, xw[l]+xw[511-l]
__device__ __half gAv[(size_t)M_ * LH];        // 33.5 MB, xw[l]-xw[511-l]
__device__ __half gBc[LH * KH];                // cos basis (l<256, k<256)
__device__ __half gBs[LH * KH];                // sin basis

// ---------------- helpers ----------------
__device__ __forceinline__ uint32_t smem_u32(const void* p) {
    uint32_t a;
    asm("{ .reg .u64 t; cvta.to.shared.u64 t, %1; cvt.u32.u64 %0, t; }" : "=r"(a) : "l"(p));
    return a;
}
#define CP_ASYNC16(dst, src) asm volatile("cp.async.cg.shared.global [%0], [%1], 16;" :: "r"(dst), "l"(src))
#define CP_COMMIT() asm volatile("cp.async.commit_group;" ::: "memory")

#define LDSM4(R, addr) \
    asm volatile("ldmatrix.sync.aligned.m8n8.x4.shared.b16 {%0,%1,%2,%3}, [%4];" \
        : "=r"((R)[0]), "=r"((R)[1]), "=r"((R)[2]), "=r"((R)[3]) : "r"(addr))
#define LDSM4T(R, addr) \
    asm volatile("ldmatrix.sync.aligned.m8n8.x4.trans.shared.b16 {%0,%1,%2,%3}, [%4];" \
        : "=r"((R)[0]), "=r"((R)[1]), "=r"((R)[2]), "=r"((R)[3]) : "r"(addr))

#define MMA16816(D, A, B0, B1) \
    asm volatile("mma.sync.aligned.m16n8k16.row.col.f32.f16.f16.f32 " \
        "{%0,%1,%2,%3}, {%4,%5,%6,%7}, {%8,%9}, {%0,%1,%2,%3};" \
        : "+f"((D)[0]), "+f"((D)[1]), "+f"((D)[2]), "+f"((D)[3]) \
        : "r"((A)[0]), "r"((A)[1]), "r"((A)[2]), "r"((A)[3]), "r"(B0), "r"(B1))

// ---------------- prep 1: basis (fp16, l<256, k<256) + window (fp32) ----------
__global__ void precompute_kernel(const float* __restrict__ a,
                                  const float* __restrict__ sigma) {
    const int idx = blockIdx.x * blockDim.x + threadIdx.x;
    const float c = (float)(6.283185307179586 / 511.0);
    if (idx < LH * KH) {
        const int l = idx / KH, k = idx - l * KH;
        float s, cc;
        sincosf(c * (float)(l * k), &s, &cc);
        gBc[idx] = __float2half(cc);
        gBs[idx] = __float2half(s);
    }
    if (idx < D_ * L_) {
        const int d = idx / L_, l = idx - d * L_;
        const float ad = a[d];
        const float w = ad - (1.0f - ad) * cosf(c * (float)l);
        g_w[idx] = w * expf(sigma[d] * (1.0f / 511.0f));
    }
}

// ---------------- prep 2: fold xw into u (even) / v (odd) halves ------------
__global__ __launch_bounds__(256)
void fold_a_kernel(const float* __restrict__ x) {
    const size_t g = (size_t)blockIdx.x * blockDim.x + threadIdx.x; // (m, lq)
    if (g >= (size_t)M_ * (LH / 4)) return;
    const int m  = (int)(g >> 6);          // LH/4 = 64
    const int lq = (int)(g & 63);
    const int d  = m & (D_ - 1);
    const float4 xf = *(const float4*)(x + (size_t)m * L_ + lq * 4);
    const float4 xm = *(const float4*)(x + (size_t)m * L_ + 508 - lq * 4);
    const float4 wf = *(const float4*)(g_w + (size_t)d * L_ + lq * 4);
    const float4 wm = *(const float4*)(g_w + (size_t)d * L_ + 508 - lq * 4);
    const float f[4]  = {xf.x * wf.x, xf.y * wf.y, xf.z * wf.z, xf.w * wf.w};
    const float mr[4] = {xm.w * wm.w, xm.z * wm.z, xm.y * wm.y, xm.x * wm.x};
    __half u[4], v[4];
#pragma unroll
    for (int i = 0; i < 4; ++i) {
        u[i] = __float2half(f[i] + mr[i]);
        v[i] = __float2half(f[i] - mr[i]);
    }
    ((uint2*)gAu)[g] = *(uint2*)u;
    ((uint2*)gAv)[g] = *(uint2*)v;
}

// ---------------- main: folded dual-GEMM + magnitude ------------------------
// Xr = Au @ C, Xi = Av @ S over K-dim 256; CTA 128(M) x 64(N), BK=64,
// 8 warps (2Mx4N), warp tile 64x16, 2 CTAs/SM, 2-stage pipeline.
#define BK 64
#define NCH (LH / BK)            // 4 chunks
#define PITCH 144                // 128B data + 16B pad (conflict-free ldmatrix)
#define SA_BYTES (128 * PITCH)   // 18432 per A tile
#define SB_BYTES (64 * PITCH)    // 9216 per B matrix
#define SB_BASE (2 * SA_BYTES)   // Au, Av, then C, S
#define STAGE (SB_BASE + 2 * SB_BYTES)  // 55296
#define SMEM_TOTAL (2 * STAGE)          // 110592 -> 2 CTAs/SM (221KB < 228KB)

__device__ __forceinline__ void load_chunk(uint32_t sbuf, int row0, int col0,
                                           int l0, int tid) {
    // Au, Av: 2 x 128 rows x 8 (16B units) = 2048 -> 8 per thread
#pragma unroll
    for (int p = 0; p < 8; ++p) {
        const int u = tid + p * 256;
        const int mat = u >> 10;
        const int r = (u >> 3) & 127;
        const int cu = u & 7;
        const __half* g = mat ? gAv : gAu;
        const __half* src = g + (size_t)(row0 + r) * LH + l0 + cu * 8;
        CP_ASYNC16(sbuf + mat * SA_BYTES + r * PITCH + cu * 16, src);
    }
    // B: 2 matrices x 64 rows x 8 (16B units) = 1024 -> 4 per thread
#pragma unroll
    for (int p = 0; p < 4; ++p) {
        const int u = tid + p * 256;
        const int mat = u >> 9;
        const int r = (u >> 3) & 63;
        const int cu = u & 7;
        const __half* g = mat ? gBs : gBc;
        const __half* src = g + (size_t)(l0 + r) * KH + col0 + cu * 8;
        CP_ASYNC16(sbuf + SB_BASE + mat * SB_BYTES + r * PITCH + cu * 16, src);
    }
}

__global__ __launch_bounds__(256, 2)
void spectro_mma_kernel(float* __restrict__ out) {
    extern __shared__ char smem[];
    const uint32_t sbase = smem_u32(smem);
    const int tid = threadIdx.x;
    const int wid = tid >> 5;
    const int lid = tid & 31;
    const int col0 = blockIdx.x * 64;    // 4 col tiles (k < 256)
    const int row0 = blockIdx.y * 128;   // 512 row tiles
    const int wm = wid >> 2;             // 0..1 (M)
    const int wn = wid & 3;              // 0..3 (N)

    float accR[4][2][4];
    float accI[4][2][4];
#pragma unroll
    for (int mt = 0; mt < 4; ++mt)
#pragma unroll
        for (int nt = 0; nt < 2; ++nt)
#pragma unroll
            for (int j = 0; j < 4; ++j) { accR[mt][nt][j] = 0.f; accI[mt][nt][j] = 0.f; }

    const int g8 = lid >> 3;       // 0..3
    const int lr = lid & 7;        // row within 8x8

    load_chunk(sbase, row0, col0, 0, tid);
    CP_COMMIT();

    for (int c = 0; c < NCH; ++c) {
        if (c + 1 < NCH) {
            load_chunk(sbase + ((c + 1) & 1) * STAGE, row0, col0, (c + 1) * BK, tid);
            CP_COMMIT();
            asm volatile("cp.async.wait_group 1;" ::: "memory");
        } else {
            asm volatile("cp.async.wait_group 0;" ::: "memory");
        }
        __syncthreads();

        const uint32_t sa = sbase + (c & 1) * STAGE;
        const uint32_t sb = sa + SB_BASE;
#pragma unroll
        for (int kk = 0; kk < 4; ++kk) {
            const int krow = kk * 16 + ((g8 & 1) << 3) + lr;
            const uint32_t bd = sb + krow * PITCH + wn * 32 + ((g8 >> 1) << 4);
            uint32_t bC[4], bS[4];
            LDSM4T(bC, bd);
            LDSM4T(bS, bd + SB_BYTES);
#pragma unroll
            for (int mt = 0; mt < 4; ++mt) {
                const int row = wm * 64 + mt * 16 + ((g8 & 1) << 3) + lr;
                const uint32_t ad = sa + row * PITCH + kk * 32 + ((g8 >> 1) << 4);
                uint32_t aU[4], aV[4];
                LDSM4(aU, ad);
                LDSM4(aV, ad + SA_BYTES);
#pragma unroll
                for (int nt = 0; nt < 2; ++nt) {
                    MMA16816(accR[mt][nt], aU, bC[nt * 2], bC[nt * 2 + 1]);
                    MMA16816(accI[mt][nt], aV, bS[nt * 2], bS[nt * 2 + 1]);
                }
            }
        }
        __syncthreads();
    }

    // ---- epilogue: magnitude; store column k and its mirror 511-k ----
#pragma unroll
    for (int mt = 0; mt < 4; ++mt) {
#pragma unroll
        for (int nt = 0; nt < 2; ++nt) {
            const int r0 = row0 + wm * 64 + mt * 16 + (lid >> 2);
            const int cc = col0 + wn * 16 + nt * 8 + (lid & 3) * 2;
            float2 o0, o1;
            o0.x = sqrtf(fmaf(accR[mt][nt][0], accR[mt][nt][0],
                              accI[mt][nt][0] * accI[mt][nt][0]));
            o0.y = sqrtf(fmaf(accR[mt][nt][1], accR[mt][nt][1],
                              accI[mt][nt][1] * accI[mt][nt][1]));
            o1.x = sqrtf(fmaf(accR[mt][nt][2], accR[mt][nt][2],
                              accI[mt][nt][2] * accI[mt][nt][2]));
            o1.y = sqrtf(fmaf(accR[mt][nt][3], accR[mt][nt][3],
                              accI[mt][nt][3] * accI[mt][nt][3]));
            float* row_a = out + (size_t)r0 * K_;
            float* row_b = out + (size_t)(r0 + 8) * K_;
            *(float2*)(row_a + cc) = o0;
            *(float2*)(row_b + cc) = o1;
            float2 m0 = {o0.y, o0.x};
            float2 m1 = {o1.y, o1.x};
            *(float2*)(row_a + 510 - cc) = m0;
            *(float2*)(row_b + 510 - cc) = m1;
        }
    }
}

// ---------------------------------------------------------------------------
extern "C" void kernel_launch(void* const* d_in, const int* in_sizes, int n_in,
                              void* d_out, int out_size) {
    const float* x     = (const float*)d_in[0];  // (N, D, L)
    const float* a     = (const float*)d_in[1];  // (D,)
    const float* sigma = (const float*)d_in[2];  // (D,)
    float* out = (float*)d_out;                  // (N, D, K)

    precompute_kernel<<<(D_ * L_ + 255) / 256, 256>>>(a, sigma);
    fold_a_kernel<<<(M_ * (LH / 4) + 255) / 256, 256>>>(x);

    static bool attr_set = false;
    if (!attr_set) {
        cudaFuncSetAttribute(spectro_mma_kernel,
                             cudaFuncAttributeMaxDynamicSharedMemorySize, SMEM_TOTAL);
        attr_set = true;
    }
    dim3 grid(KH / 64, M_ / 128);   // (4, 512)
    spectro_mma_kernel<<<grid, 256, SMEM_TOTAL>>>(out);
}